// round 2
// baseline (speedup 1.0000x reference)
#include <cuda_runtime.h>
#include <cuda_bf16.h>

// Problem constants
#define NB 256   // batch (both i and j axes)
#define ND 64    // dim_z
#define NS 32    // samples
#define NPOINTS_PER_D (NB * NS)          // 8192 (j,s) points per dim d
#define P 4                              // points per thread
#define THREADS 256
#define POINTS_PER_BLOCK (THREADS * P)   // 1024
#define YTILES (NPOINTS_PER_D / POINTS_PER_BLOCK) // 8

__device__ __forceinline__ float ex2_approx(float x) {
    float r;
    asm("ex2.approx.ftz.f32 %0, %1;" : "=f"(r) : "f"(x));
    return r;
}

__global__ void zero_out_kernel(float* out) { out[0] = 0.0f; }

__global__ __launch_bounds__(THREADS, 8)
void kl_kernel(const float* __restrict__ prior_mean,
               const float* __restrict__ prior_logvar,
               const float* __restrict__ post_mean,
               const float* __restrict__ post_logvar,
               const float* __restrict__ eps,
               float* __restrict__ out)
{
    constexpr float LOG_2PI  = 1.8378770664093453f;
    constexpr float INV_LN2  = 1.4426950408889634f;
    constexpr float LOG_B    = 5.545177444479562f;   // ln(256)
    constexpr float VAR_EPS  = 1.0e-4f;

    __shared__ float sm_m[NB];
    __shared__ float sm_c0[NB];   // base-2 prescaled constant term
    __shared__ float sm_inv[NB];  // base-2 prescaled 1/(2 e^lv + eps)
    __shared__ float sm_red[THREADS / 32];

    const int d = blockIdx.x;
    const int t = threadIdx.x;

    // Load the 256 posterior (i) params for this dim d into shared memory.
    {
        float m  = post_mean[t * ND + d];
        float lv = post_logvar[t * ND + d];
        sm_m[t]   = m;
        sm_c0[t]  = (-0.5f * LOG_2PI - 0.5f * lv) * INV_LN2;
        sm_inv[t] = INV_LN2 / (2.0f * __expf(lv) + VAR_EPS);
    }
    __syncthreads();

    // Each thread owns P sample points (j,s) for this d.
    const int qbase = blockIdx.y * POINTS_PER_BLOCK + t;

    float z[P];
    float acc[P];
#pragma unroll
    for (int p = 0; p < P; p++) {
        int q = qbase + p * THREADS;
        int j = q >> 5;        // q / NS
        int s = q & 31;        // q % NS
        float pmj  = post_mean[j * ND + d];
        float plvj = post_logvar[j * ND + d];
        float e    = eps[(j * ND + d) * NS + s];
        z[p]   = fmaf(e, __expf(0.5f * plvj), pmj);
        acc[p] = 0.0f;
    }

    // Main loop: sum_i exp(logpdf_i(z_p)) in base-2 domain, unstabilized.
    // Safe: w <= c0/ln2 ~ 1.6 (no overflow); the i==j diagonal term keeps
    // the sum >= ~e^-14 (no total underflow).
#pragma unroll 4
    for (int i = 0; i < NB; i++) {
        float m   = sm_m[i];
        float c0  = sm_c0[i];
        float inv = sm_inv[i];
#pragma unroll
        for (int p = 0; p < P; p++) {
            float dd = z[p] - m;
            float w  = fmaf(dd * dd, -inv, c0);
            acc[p] += ex2_approx(w);
        }
    }

    // Epilogue: lse, prior log-density, density gap.
    float local = 0.0f;
#pragma unroll
    for (int p = 0; p < P; p++) {
        int q = qbase + p * THREADS;
        int j = q >> 5;
        float lse = __logf(acc[p]);   // ln(sum 2^w) = ln(sum e^v)

        float pm  = prior_mean[j * ND + d];
        float plv = prior_logvar[j * ND + d];
        float dd  = z[p] - pm;
        float logprior = -0.5f * LOG_2PI - 0.5f * plv
                         - dd * dd / (2.0f * __expf(plv) + VAR_EPS);

        local += (lse - LOG_B) - logprior;
    }

    // Block reduction -> atomicAdd, scaled by 1/(B*S) (mean over j, mean over s, sum over d).
#pragma unroll
    for (int off = 16; off > 0; off >>= 1)
        local += __shfl_xor_sync(0xffffffffu, local, off);

    int lane = t & 31, warp = t >> 5;
    if (lane == 0) sm_red[warp] = local;
    __syncthreads();
    if (warp == 0) {
        float v = (lane < THREADS / 32) ? sm_red[lane] : 0.0f;
#pragma unroll
        for (int off = 4; off > 0; off >>= 1)
            v += __shfl_xor_sync(0xffffffffu, v, off);
        if (lane == 0)
            atomicAdd(out, v * (1.0f / (float)(NB * NS)));
    }
}

extern "C" void kernel_launch(void* const* d_in, const int* in_sizes, int n_in,
                              void* d_out, int out_size) {
    const float* prior_mean   = (const float*)d_in[0];
    const float* prior_logvar = (const float*)d_in[1];
    const float* post_mean    = (const float*)d_in[2];
    const float* post_logvar  = (const float*)d_in[3];
    const float* eps          = (const float*)d_in[4];
    float* out = (float*)d_out;

    zero_out_kernel<<<1, 1>>>(out);
    dim3 grid(ND, YTILES);
    kl_kernel<<<grid, THREADS>>>(prior_mean, prior_logvar, post_mean,
                                 post_logvar, eps, out);
}

// round 4
// speedup vs baseline: 1.1231x; 1.1231x over previous
#include <cuda_runtime.h>
#include <cuda_bf16.h>

// Problem constants
#define NB 256   // batch (both i and j axes)
#define ND 64    // dim_z
#define NS 32    // samples
#define NPOINTS_PER_D (NB * NS)          // 8192 (j,s) points per dim d
#define P 4                              // points per thread
#define THREADS 128
#define POINTS_PER_BLOCK (THREADS * P)   // 512
#define YTILES (NPOINTS_PER_D / POINTS_PER_BLOCK) // 16

__device__ __forceinline__ float ex2_approx(float x) {
    float r;
    asm("ex2.approx.ftz.f32 %0, %1;" : "=f"(r) : "f"(x));
    return r;
}

__global__ void zero_out_kernel(float* out) { out[0] = 0.0f; }

__global__ __launch_bounds__(THREADS, 16)
void kl_kernel(const float* __restrict__ prior_mean,
               const float* __restrict__ prior_logvar,
               const float* __restrict__ post_mean,
               const float* __restrict__ post_logvar,
               const float* __restrict__ eps,
               float* __restrict__ out)
{
    constexpr float LOG_2PI  = 1.8378770664093453f;
    constexpr float INV_LN2  = 1.4426950408889634f;
    constexpr float LOG_B    = 5.545177444479562f;   // ln(256)
    constexpr float VAR_EPS  = 1.0e-4f;

    // Per-posterior-i quadratic coefficients in base-2 domain:
    //   w_i(z) = a*z^2 + b*z + c,  a = -inv, b = 2*inv*m, c = c0 - inv*m^2
    // packed as float4 so the inner loop does ONE LDS.128 per i.
    __shared__ float4 sm_p[NB];
    __shared__ float  sm_red[THREADS / 32];

    const int d = blockIdx.x;
    const int t = threadIdx.x;

    // Load the 256 posterior (i) params for this dim d (2 per thread).
#pragma unroll
    for (int r = 0; r < NB / THREADS; r++) {
        int i = t + r * THREADS;
        float m   = post_mean[i * ND + d];
        float lv  = post_logvar[i * ND + d];
        float inv = INV_LN2 / (2.0f * __expf(lv) + VAR_EPS);
        float c0  = (-0.5f * LOG_2PI - 0.5f * lv) * INV_LN2;
        float4 pr;
        pr.x = -inv;
        pr.y = 2.0f * inv * m;
        pr.z = fmaf(-inv, m * m, c0);
        pr.w = 0.0f;
        sm_p[i] = pr;
    }
    __syncthreads();

    // Each thread owns P sample points (j,s) for this d.
    const int qbase = blockIdx.y * POINTS_PER_BLOCK + t;

    float z[P];
    float acc[P];
#pragma unroll
    for (int p = 0; p < P; p++) {
        int q = qbase + p * THREADS;
        int j = q >> 5;        // q / NS
        int s = q & 31;        // q % NS
        float pmj  = post_mean[j * ND + d];
        float plvj = post_logvar[j * ND + d];
        float e    = eps[(j * ND + d) * NS + s];
        z[p]   = fmaf(e, __expf(0.5f * plvj), pmj);
        acc[p] = 0.0f;
    }

    // Main loop: sum_i 2^{w_i(z_p)}, unstabilized single pass.
    // Safe: w <= c0/ln2 ~ 1.6 (no overflow); the i==j diagonal term keeps
    // the sum >= ~e^-14 (no total underflow). Expansion error in w is
    // O(1e-4) absolute -> O(7e-5) relative in 2^w, well under tolerance.
#pragma unroll 4
    for (int i = 0; i < NB; i++) {
        float4 pr = sm_p[i];
#pragma unroll
        for (int p = 0; p < P; p++) {
            float t0 = fmaf(z[p], pr.x, pr.y);
            float w  = fmaf(z[p], t0, pr.z);
            acc[p] += ex2_approx(w);
        }
    }

    // Epilogue: lse, prior log-density, density gap.
    float local = 0.0f;
#pragma unroll
    for (int p = 0; p < P; p++) {
        int q = qbase + p * THREADS;
        int j = q >> 5;
        float lse = __logf(acc[p]);   // ln(sum 2^w) = ln(sum e^v)

        float pm  = prior_mean[j * ND + d];
        float plv = prior_logvar[j * ND + d];
        float dd  = z[p] - pm;
        float logprior = -0.5f * LOG_2PI - 0.5f * plv
                         - dd * dd / (2.0f * __expf(plv) + VAR_EPS);

        local += (lse - LOG_B) - logprior;
    }

    // Block reduction -> atomicAdd, scaled by 1/(B*S).
#pragma unroll
    for (int off = 16; off > 0; off >>= 1)
        local += __shfl_xor_sync(0xffffffffu, local, off);

    int lane = t & 31, warp = t >> 5;
    if (lane == 0) sm_red[warp] = local;
    __syncthreads();
    if (warp == 0) {
        float v = (lane < THREADS / 32) ? sm_red[lane] : 0.0f;
#pragma unroll
        for (int off = 2; off > 0; off >>= 1)
            v += __shfl_xor_sync(0xffffffffu, v, off);
        if (lane == 0)
            atomicAdd(out, v * (1.0f / (float)(NB * NS)));
    }
}

extern "C" void kernel_launch(void* const* d_in, const int* in_sizes, int n_in,
                              void* d_out, int out_size) {
    const float* prior_mean   = (const float*)d_in[0];
    const float* prior_logvar = (const float*)d_in[1];
    const float* post_mean    = (const float*)d_in[2];
    const float* post_logvar  = (const float*)d_in[3];
    const float* eps          = (const float*)d_in[4];
    float* out = (float*)d_out;

    zero_out_kernel<<<1, 1>>>(out);
    dim3 grid(ND, YTILES);
    kl_kernel<<<grid, THREADS>>>(prior_mean, prior_logvar, post_mean,
                                 post_logvar, eps, out);
}